// round 3
// baseline (speedup 1.0000x reference)
#include <cuda_runtime.h>
#include <math_constants.h>

// Problem constants
#define B 32
#define Q 10000
#define C 80
#define TOPK 200
#define NCHUNK 16
#define CHUNK 625            // Q / NCHUNK
#define CH_PAD 1024          // next pow2 >= CHUNK
#define MERGE_N 4096         // next pow2 >= NCHUNK*TOPK = 3200

// Scratch (device globals; no allocation allowed)
__device__ unsigned long long g_keys[B * Q];      // (score_bits<<32) | ~q
__device__ unsigned char       g_cls[B * Q];      // argmax class (0..79)
__device__ unsigned long long g_cand[B * NCHUNK * TOPK];
__device__ unsigned long long g_top[B * TOPK];

// ---------------------------------------------------------------------------
// K1: per-query softmax-max score + argmax class. One warp per query.
// score = exp(max - max) / sum(exp(l - max)) = 1 / sumexp  (matches XLA softmax)
// ---------------------------------------------------------------------------
__global__ __launch_bounds__(256) void score_kernel(const float* __restrict__ logits) {
    int w = (blockIdx.x * 256 + threadIdx.x) >> 5;   // global warp id = query id
    int lane = threadIdx.x & 31;
    if (w >= B * Q) return;
    const float* p = logits + (size_t)w * C;

    float v0 = p[lane];
    float v1 = p[32 + lane];
    float v2 = (lane < 16) ? p[64 + lane] : -CUDART_INF_F;

    // lane-local max with first-occurrence tie-break (strict > keeps lower idx)
    float m = v0; int mi = lane;
    if (v1 > m) { m = v1; mi = 32 + lane; }
    if (v2 > m) { m = v2; mi = 64 + lane; }
    // warp argmax, tie -> lower index
    #pragma unroll
    for (int o = 16; o; o >>= 1) {
        float om = __shfl_xor_sync(0xffffffffu, m, o);
        int   oi = __shfl_xor_sync(0xffffffffu, mi, o);
        if (om > m || (om == m && oi < mi)) { m = om; mi = oi; }
    }
    // sumexp
    float e = expf(v0 - m) + expf(v1 - m) + ((lane < 16) ? expf(v2 - m) : 0.0f);
    #pragma unroll
    for (int o = 16; o; o >>= 1) e += __shfl_xor_sync(0xffffffffu, e, o);

    if (lane == 0) {
        float score = 1.0f / e;                      // positive in (0,1]
        int q = w % Q;
        unsigned long long key =
            ((unsigned long long)__float_as_uint(score) << 32) |
            (unsigned int)(~(unsigned int)q);        // stable tie-break: lower q = bigger key
        g_keys[w] = key;
        g_cls[w]  = (unsigned char)mi;
    }
}

// ---------------------------------------------------------------------------
// Bitonic sort (descending) helper on shared u64 array of size n (pow2)
// ---------------------------------------------------------------------------
__device__ __forceinline__ void bitonic_desc(unsigned long long* s, int n, int tid, int nthr) {
    for (int k = 2; k <= n; k <<= 1) {
        for (int j = k >> 1; j; j >>= 1) {
            for (int i = tid; i < n; i += nthr) {
                int ixj = i ^ j;
                if (ixj > i) {
                    bool up = (i & k) == 0;          // descending final order
                    unsigned long long a = s[i], b2 = s[ixj];
                    bool sw = up ? (a < b2) : (a > b2);
                    if (sw) { s[i] = b2; s[ixj] = a; }
                }
            }
            __syncthreads();
        }
    }
}

// ---------------------------------------------------------------------------
// K2: per-(batch,chunk) sort 625 keys (padded to 1024), emit top-200.
// Any global top-200 element is within the top-200 of its chunk.
// ---------------------------------------------------------------------------
__global__ __launch_bounds__(512) void chunk_sort_kernel() {
    __shared__ unsigned long long s[CH_PAD];
    int b = blockIdx.x >> 4;
    int c = blockIdx.x & 15;
    int base = b * Q + c * CHUNK;
    for (int i = threadIdx.x; i < CH_PAD; i += 512)
        s[i] = (i < CHUNK) ? g_keys[base + i] : 0ULL;
    __syncthreads();
    bitonic_desc(s, CH_PAD, threadIdx.x, 512);
    unsigned long long* out = g_cand + (b * NCHUNK + c) * TOPK;
    for (int i = threadIdx.x; i < TOPK; i += 512) out[i] = s[i];
}

// ---------------------------------------------------------------------------
// K3: per-batch merge of 16*200 candidates (padded to 4096), emit global top-200.
// ---------------------------------------------------------------------------
__global__ __launch_bounds__(1024) void merge_kernel() {
    __shared__ unsigned long long s[MERGE_N];
    int b = blockIdx.x;
    const unsigned long long* in = g_cand + b * NCHUNK * TOPK;
    for (int i = threadIdx.x; i < MERGE_N; i += 1024)
        s[i] = (i < NCHUNK * TOPK) ? in[i] : 0ULL;
    __syncthreads();
    bitonic_desc(s, MERGE_N, threadIdx.x, 1024);
    for (int i = threadIdx.x; i < TOPK; i += 1024) g_top[b * TOPK + i] = s[i];
}

// ---------------------------------------------------------------------------
// K4: per-batch greedy NMS over the 200 sorted candidates + output write.
// Serial over p (as in the reference), warp-parallel suppression.
// Output is FLOAT32 (harness/output dtype): values are the indices / -1 / 0.
// ---------------------------------------------------------------------------
__global__ __launch_bounds__(256) void nms_kernel(const float* __restrict__ seg,
                                                  float* __restrict__ out) {
    __shared__ float sx1[TOPK], sx2[TOPK];
    __shared__ int sq[TOPK];
    __shared__ unsigned char scls[TOPK];
    __shared__ unsigned char sact[TOPK];
    int b = blockIdx.x;
    int t = threadIdx.x;

    if (t < TOPK) {
        unsigned long long key = g_top[b * TOPK + t];
        int q = (int)(~(unsigned int)key);
        sq[t] = q;
        int gi = b * Q + q;
        scls[t] = g_cls[gi];
        sx1[t] = seg[2 * (size_t)gi];
        sx2[t] = seg[2 * (size_t)gi + 1];
        sact[t] = 1;
    }
    // init output: -1 padding for keep half, zeros for second half (float values)
    for (int i = t; i < TOPK; i += 256) {
        out[b * TOPK + i] = -1.0f;
        out[(B + b) * TOPK + i] = 0.0f;
    }
    __syncthreads();

    if (t < 32) {
        int cnt = 0;
        for (int p = 0; p < TOPK; p++) {
            bool act = (sact[p] != 0);
            if (act) {
                if (t == 0) out[b * TOPK + cnt] = (float)sq[p];
                cnt++;
                float px1 = sx1[p], px2 = sx2[p];
                unsigned char pc = scls[p];
                for (int j = p + 1 + t; j < TOPK; j += 32) {
                    if (sact[j] && scls[j] == pc) {
                        // inter > 0  <=>  min(x2) - max(x1) > 0  (clip irrelevant for >0 test)
                        float inter = fminf(sx2[j], px2) - fmaxf(sx1[j], px1);
                        if (inter > 0.0f) sact[j] = 0;
                    }
                }
            }
            __syncwarp();
        }
    }
}

// ---------------------------------------------------------------------------
extern "C" void kernel_launch(void* const* d_in, const int* in_sizes, int n_in,
                              void* d_out, int out_size) {
    const float* logits = (const float*)d_in[0];   // [B,Q,C] f32
    const float* seg    = (const float*)d_in[1];   // [B,Q,2] f32
    float* out = (float*)d_out;                    // [2B, TOPK] as float32 values

    // K1: one warp per query; 320000 warps / 8 warps-per-block = 40000 blocks
    score_kernel<<<(B * Q) / 8, 256>>>(logits);
    // K2: 32 batches * 16 chunks
    chunk_sort_kernel<<<B * NCHUNK, 512>>>();
    // K3: one block per batch
    merge_kernel<<<B, 1024>>>();
    // K4: one block per batch
    nms_kernel<<<B, 256>>>(seg, out);
}

// round 4
// speedup vs baseline: 1.6631x; 1.6631x over previous
#include <cuda_runtime.h>
#include <math_constants.h>

// Problem constants
#define B 32
#define Q 10000
#define C 80
#define TOPK 200
#define NCHUNK 10
#define CHUNK 1000           // Q / NCHUNK
#define CH_PAD 1024          // next pow2 >= CHUNK
#define CAND (NCHUNK * TOPK) // 2000
#define MERGE_N 2048         // next pow2 >= CAND
#define NW 7                 // 224 bits >= 200

// Scratch (device globals; no allocation allowed)
__device__ unsigned long long g_keys[B * Q];        // (score_bits<<32) | ~q
__device__ unsigned char      g_cls[B * Q];         // argmax class (0..79)
__device__ unsigned long long g_cand[B * CAND];

// ---------------------------------------------------------------------------
// K1: per-query softmax-max score + argmax class. One warp per query.
// score = 1 / sum(exp(l - max))   (max term contributes exp(0)=1)
// ---------------------------------------------------------------------------
__global__ __launch_bounds__(256) void score_kernel(const float* __restrict__ logits) {
    int w = (blockIdx.x * 256 + threadIdx.x) >> 5;   // global warp id = query id
    int lane = threadIdx.x & 31;
    if (w >= B * Q) return;
    const float* p = logits + (size_t)w * C;

    float v0 = p[lane];
    float v1 = p[32 + lane];
    float v2 = (lane < 16) ? p[64 + lane] : -CUDART_INF_F;

    // lane-local max with first-occurrence tie-break (strict > keeps lower idx)
    float m = v0; int mi = lane;
    if (v1 > m) { m = v1; mi = 32 + lane; }
    if (v2 > m) { m = v2; mi = 64 + lane; }
    // warp argmax, tie -> lower index
    #pragma unroll
    for (int o = 16; o; o >>= 1) {
        float om = __shfl_xor_sync(0xffffffffu, m, o);
        int   oi = __shfl_xor_sync(0xffffffffu, mi, o);
        if (om > m || (om == m && oi < mi)) { m = om; mi = oi; }
    }
    // sumexp
    float e = expf(v0 - m) + expf(v1 - m) + ((lane < 16) ? expf(v2 - m) : 0.0f);
    #pragma unroll
    for (int o = 16; o; o >>= 1) e += __shfl_xor_sync(0xffffffffu, e, o);

    if (lane == 0) {
        float score = 1.0f / e;                      // positive in (0,1]
        int q = w % Q;
        unsigned long long key =
            ((unsigned long long)__float_as_uint(score) << 32) |
            (unsigned int)(~(unsigned int)q);        // stable: lower q = bigger key
        g_keys[w] = key;
        g_cls[w]  = (unsigned char)mi;
    }
}

// ---------------------------------------------------------------------------
// Bitonic sort (descending) on shared u64 array of size n (pow2)
// ---------------------------------------------------------------------------
__device__ __forceinline__ void bitonic_desc(unsigned long long* s, int n, int tid, int nthr) {
    for (int k = 2; k <= n; k <<= 1) {
        for (int j = k >> 1; j; j >>= 1) {
            for (int i = tid; i < n; i += nthr) {
                int ixj = i ^ j;
                if (ixj > i) {
                    bool up = (i & k) == 0;          // descending final order
                    unsigned long long a = s[i], b2 = s[ixj];
                    bool sw = up ? (a < b2) : (a > b2);
                    if (sw) { s[i] = b2; s[ixj] = a; }
                }
            }
            __syncthreads();
        }
    }
}

// ---------------------------------------------------------------------------
// K2: per-(batch,chunk) sort 1000 keys (padded to 1024), emit top-200.
// Any global top-200 element is within the top-200 of its chunk.
// ---------------------------------------------------------------------------
__global__ __launch_bounds__(512) void chunk_sort_kernel() {
    __shared__ unsigned long long s[CH_PAD];
    int b = blockIdx.x / NCHUNK;
    int c = blockIdx.x % NCHUNK;
    int base = b * Q + c * CHUNK;
    for (int i = threadIdx.x; i < CH_PAD; i += 512)
        s[i] = (i < CHUNK) ? g_keys[base + i] : 0ULL;
    __syncthreads();
    bitonic_desc(s, CH_PAD, threadIdx.x, 512);
    unsigned long long* out = g_cand + (b * NCHUNK + c) * TOPK;
    for (int i = threadIdx.x; i < TOPK; i += 512) out[i] = s[i];
}

// ---------------------------------------------------------------------------
// K3 (fused): per-batch merge of 2000 candidates -> global top-200, then
// greedy NMS via suppression bit-matrix + register-resident active mask.
// One block of 1024 threads per batch. Output dtype is FLOAT32.
// ---------------------------------------------------------------------------
__global__ __launch_bounds__(1024) void merge_nms_kernel(const float* __restrict__ seg,
                                                         float* __restrict__ out) {
    __shared__ unsigned long long s[MERGE_N];   // 16 KB
    __shared__ float sx1[TOPK], sx2[TOPK];
    __shared__ int   sq[TOPK];
    __shared__ int   scls[TOPK];
    __shared__ unsigned int smat[TOPK * NW];    // suppression matrix rows (5.6 KB)
    __shared__ unsigned int srow[TOPK];         // row-nonzero flags
    __shared__ unsigned int sact[NW];           // final active mask
    __shared__ unsigned int spre[NW];           // word popcount prefix

    int b = blockIdx.x;
    int t = threadIdx.x;

    // ---- merge: sort 2000 candidates (pad to 2048) descending ----
    const unsigned long long* in = g_cand + b * CAND;
    s[t]        = (t < CAND)          ? in[t]        : 0ULL;
    s[t + 1024] = (t + 1024 < CAND)   ? in[t + 1024] : 0ULL;
    __syncthreads();
    bitonic_desc(s, MERGE_N, t, 1024);

    // ---- gather top-200 candidate data ----
    if (t < TOPK) {
        unsigned long long key = s[t];
        int q = (int)(~(unsigned int)key);
        sq[t] = q;
        int gi = b * Q + q;
        scls[t] = g_cls[gi];
        float2 xy = ((const float2*)seg)[gi];
        sx1[t] = xy.x; sx2[t] = xy.y;
        // init output: -1 padding for keep half, zeros for second half
        out[b * TOPK + t]       = -1.0f;
        out[(B + b) * TOPK + t] = 0.0f;
    }
    __syncthreads();

    // ---- build suppression matrix: word e=(p,w) covers j in [32w, 32w+32) ----
    for (int e = t; e < TOPK * NW; e += 1024) {
        int p = e / NW, w = e % NW;
        float px1 = sx1[p], px2 = sx2[p];
        int pc = scls[p];
        unsigned m = 0;
        int jbase = w * 32;
        #pragma unroll 8
        for (int bit = 0; bit < 32; bit++) {
            int j = jbase + bit;
            if (j < TOPK && j > p && scls[j] == pc) {
                // inter > 0  <=>  min(x2) - max(x1) > 0 (clip irrelevant for >0 test)
                float inter = fminf(sx2[j], px2) - fmaxf(sx1[j], px1);
                if (inter > 0.0f) m |= (1u << bit);
            }
        }
        smat[e] = m;
    }
    __syncthreads();
    if (t < TOPK) {
        unsigned o = 0;
        #pragma unroll
        for (int w = 0; w < NW; w++) o |= smat[t * NW + w];
        srow[t] = o;
    }
    __syncthreads();

    // ---- serial greedy scan: warp 0, active mask in registers (lane l = word l)
    if (t < 32) {
        unsigned act = (t < 6) ? 0xFFFFFFFFu : ((t == 6) ? 0x000000FFu : 0u);
        for (int p = 0; p < TOPK; p++) {
            unsigned rnz = srow[p];                       // broadcast LDS
            if (rnz) {                                    // uniform branch
                unsigned aw = __shfl_sync(0xffffffffu, act, p >> 5);
                if (aw & (1u << (p & 31))) {
                    if (t < NW) act &= ~smat[p * NW + t];
                }
            }
        }
        if (t < NW) sact[t] = act;
    }
    __syncthreads();
    if (t == 0) {
        unsigned c = 0;
        #pragma unroll
        for (int w = 0; w < NW; w++) { spre[w] = c; c += __popc(sact[w]); }
    }
    __syncthreads();

    // ---- parallel write-out: rank = #active with smaller p ----
    if (t < TOPK) {
        unsigned w = (unsigned)t >> 5, bmask = 1u << (t & 31);
        unsigned aw = sact[w];
        if (aw & bmask) {
            int rank = spre[w] + __popc(aw & (bmask - 1));
            out[b * TOPK + rank] = (float)sq[t];
        }
    }
}

// ---------------------------------------------------------------------------
extern "C" void kernel_launch(void* const* d_in, const int* in_sizes, int n_in,
                              void* d_out, int out_size) {
    const float* logits = (const float*)d_in[0];   // [B,Q,C] f32
    const float* seg    = (const float*)d_in[1];   // [B,Q,2] f32
    float* out = (float*)d_out;                    // [2B, TOPK] float32 values

    score_kernel<<<(B * Q) / 8, 256>>>(logits);          // 40000 blocks
    chunk_sort_kernel<<<B * NCHUNK, 512>>>();            // 320 blocks
    merge_nms_kernel<<<B, 1024>>>(seg, out);             // 32 blocks
}

// round 8
// speedup vs baseline: 3.2939x; 1.9806x over previous
#include <cuda_runtime.h>
#include <math_constants.h>

// Problem constants
#define B 32
#define Q 10000
#define C 80
#define TOPK 200
#define NW 7                   // 224 bits >= 200

// K1 tiling
#define ROWS 128               // queries per block
#define RPAD 21                // row stride in float4 units (odd -> conflict-free LDS)
#define NF4 20                 // 80 floats = 20 float4 per row

// K2 selection
#define NBKT 1792              // (0x3F800000 - 0x3C000000) >> 15
#define BKT_BASE 0x3C000000u
#define BKT_SHIFT 15
#define NGRP 28                // 1792 / 64
#define CANDCAP 1024

// Scratch: scores only (class is computed lazily for selected candidates)
__device__ unsigned int g_score[B * Q];

// ---------------------------------------------------------------------------
// K1: thread-per-query score. Coalesced float4 staging into smem, then each
// thread reduces its own row. Arithmetic replicates R4's warp version exactly:
//   per-"lane" partial ep[l] = exp(v[l]-m) + exp(v[l+32]-m) (+ exp(v[l+64]-m), l<16)
//   then xor-butterfly o = 16,8,4,2,1 with new[l] = old[l] + old[l^o]; use l=0.
// score = 1 / e  (max term contributes exp(0)=1, matching XLA softmax-max)
// ---------------------------------------------------------------------------
__global__ __launch_bounds__(ROWS) void score_kernel(const float* __restrict__ logits) {
    __shared__ float4 s[ROWS * RPAD];          // 43008 B
    int tid = threadIdx.x;

    // stage: 128*20 = 2560 contiguous float4, fully coalesced
    const float4* gin = (const float4*)logits + (size_t)blockIdx.x * (ROWS * NF4);
    #pragma unroll
    for (int it = 0; it < NF4; it++) {
        int fi = it * ROWS + tid;
        int r = fi / NF4, c = fi % NF4;
        s[r * RPAD + c] = gin[fi];
    }
    __syncthreads();

    const float4* row = s + tid * RPAD;

    // pass 1: exact max (order-independent)
    float m = -CUDART_INF_F;
    #pragma unroll
    for (int j = 0; j < NF4; j++) {
        float4 f = row[j];
        m = fmaxf(m, fmaxf(fmaxf(f.x, f.y), fmaxf(f.z, f.w)));
    }

    // pass 2: per-lane partials in ascending column order (matches R4)
    float ep[32];
    #pragma unroll
    for (int l = 0; l < 32; l++) ep[l] = 0.0f;
    #pragma unroll
    for (int j = 0; j < NF4; j++) {
        float4 f = row[j];
        ep[(4 * j + 0) & 31] += expf(f.x - m);
        ep[(4 * j + 1) & 31] += expf(f.y - m);
        ep[(4 * j + 2) & 31] += expf(f.z - m);
        ep[(4 * j + 3) & 31] += expf(f.w - m);
    }
    // butterfly identical to the shfl_xor tree (o = 16,8,4,2,1), self-first operand order
    float e1[32], e2[32], e3[32], e4[32];
    #pragma unroll
    for (int l = 0; l < 32; l++) e1[l] = ep[l] + ep[l ^ 16];
    #pragma unroll
    for (int l = 0; l < 32; l++) e2[l] = e1[l] + e1[l ^ 8];
    #pragma unroll
    for (int l = 0; l < 32; l++) e3[l] = e2[l] + e2[l ^ 4];
    #pragma unroll
    for (int l = 0; l < 32; l++) e4[l] = e3[l] + e3[l ^ 2];
    float e = e4[0] + e4[1];

    float score = 1.0f / e;                    // positive in (0,1]
    g_score[(size_t)blockIdx.x * ROWS + tid] = __float_as_uint(score);
}

// ---------------------------------------------------------------------------
// K2 (fused, per batch): histogram top-k selection -> bitonic sort 1024 ->
// lazy argmax for the 200 winners -> bit-matrix greedy NMS -> float output.
// One block of 1024 threads per batch.
// ---------------------------------------------------------------------------
__global__ __launch_bounds__(1024) void select_nms_kernel(const float* __restrict__ logits,
                                                          const float* __restrict__ seg,
                                                          float* __restrict__ out) {
    __shared__ unsigned int hist[NBKT];
    __shared__ int gsum[NGRP];
    __shared__ int s_cb, s_cnt;
    __shared__ unsigned long long ck[CANDCAP];  // 8 KB
    __shared__ float sx1[TOPK], sx2[TOPK];
    __shared__ int   sq[TOPK], scls[TOPK];
    __shared__ unsigned int smat[TOPK * NW];    // 5.6 KB
    __shared__ unsigned int srow[TOPK];
    __shared__ unsigned int sact[NW], spre[NW];

    int b = blockIdx.x;
    int t = threadIdx.x;
    const unsigned int* sc = g_score + b * Q;

    // ---- histogram of score high-bits (monotone bucketing) ----
    for (int i = t; i < NBKT; i += 1024) hist[i] = 0;
    if (t == 0) s_cnt = 0;
    __syncthreads();
    for (int i = t; i < Q; i += 1024) {
        unsigned int v = sc[i];
        int bk = (v <= BKT_BASE) ? 0 : (int)((v - BKT_BASE) >> BKT_SHIFT);
        if (bk > NBKT - 1) bk = NBKT - 1;
        atomicAdd(&hist[bk], 1u);
    }
    __syncthreads();
    // ---- cutoff bucket: largest cb with suffix-count >= TOPK ----
    if (t < NGRP) {
        int a = 0;
        #pragma unroll 8
        for (int j = 0; j < 64; j++) a += hist[t * 64 + j];
        gsum[t] = a;
    }
    __syncthreads();
    if (t == 0) {
        int acc = 0, cb = 0;
        for (int g = NGRP - 1; g >= 0; g--) {
            if (acc + gsum[g] >= TOPK) {
                for (int c = g * 64 + 63; c >= g * 64; c--) {
                    acc += hist[c];
                    if (acc >= TOPK) { cb = c; break; }
                }
                break;
            }
            acc += gsum[g];
        }
        s_cb = cb;
    }
    __syncthreads();
    unsigned int thr = (s_cb == 0) ? 0u : (BKT_BASE + ((unsigned)s_cb << BKT_SHIFT));

    // ---- compact candidates (order fixed later by full-key sort) ----
    for (int i = t; i < Q; i += 1024) {
        unsigned int v = sc[i];
        if (v >= thr) {
            int pos = atomicAdd(&s_cnt, 1);
            if (pos < CANDCAP)
                ck[pos] = ((unsigned long long)v << 32) | (unsigned int)(~(unsigned int)i);
        }
    }
    __syncthreads();
    int cnt = s_cnt; if (cnt > CANDCAP) cnt = CANDCAP;
    for (int i = t; i < CANDCAP; i += 1024)
        if (i >= cnt) ck[i] = 0ULL;
    __syncthreads();

    // ---- bitonic sort descending (1024 keys) ----
    for (int k = 2; k <= CANDCAP; k <<= 1) {
        for (int j = k >> 1; j; j >>= 1) {
            int ixj = t ^ j;
            if (ixj > t) {
                bool up = (t & k) == 0;
                unsigned long long a = ck[t], c2 = ck[ixj];
                bool sw = up ? (a < c2) : (a > c2);
                if (sw) { ck[t] = c2; ck[ixj] = a; }
            }
            __syncthreads();
        }
    }

    // ---- gather top-200 + init output ----
    if (t < TOPK) {
        unsigned long long key = ck[t];
        int q = (int)(~(unsigned int)key);
        sq[t] = q;
        int gi = b * Q + q;
        float2 xy = ((const float2*)seg)[gi];
        sx1[t] = xy.x; sx2[t] = xy.y;
        out[b * TOPK + t]       = -1.0f;
        out[(B + b) * TOPK + t] = 0.0f;
    }
    __syncthreads();

    // ---- lazy argmax class for the 200 winners (warp per candidate) ----
    {
        int wid = t >> 5, lane = t & 31;
        for (int c = wid; c < TOPK; c += 32) {
            const float* p = logits + ((size_t)b * Q + sq[c]) * C;
            float v0 = p[lane];
            float v1 = p[32 + lane];
            float v2 = (lane < 16) ? p[64 + lane] : -CUDART_INF_F;
            float m = v0; int mi = lane;
            if (v1 > m) { m = v1; mi = 32 + lane; }
            if (v2 > m) { m = v2; mi = 64 + lane; }
            #pragma unroll
            for (int o = 16; o; o >>= 1) {
                float om = __shfl_xor_sync(0xffffffffu, m, o);
                int   oi = __shfl_xor_sync(0xffffffffu, mi, o);
                if (om > m || (om == m && oi < mi)) { m = om; mi = oi; }
            }
            if (lane == 0) scls[c] = mi;
        }
    }
    __syncthreads();

    // ---- suppression bit-matrix: word e=(p,w) covers j in [32w, 32w+32) ----
    for (int e = t; e < TOPK * NW; e += 1024) {
        int p = e / NW, w = e % NW;
        float px1 = sx1[p], px2 = sx2[p];
        int pc = scls[p];
        unsigned m = 0;
        int jbase = w * 32;
        #pragma unroll 8
        for (int bit = 0; bit < 32; bit++) {
            int j = jbase + bit;
            if (j < TOPK && j > p && scls[j] == pc) {
                float inter = fminf(sx2[j], px2) - fmaxf(sx1[j], px1);
                if (inter > 0.0f) m |= (1u << bit);
            }
        }
        smat[e] = m;
    }
    __syncthreads();
    if (t < TOPK) {
        unsigned o = 0;
        #pragma unroll
        for (int w = 0; w < NW; w++) o |= smat[t * NW + w];
        srow[t] = o;
    }
    __syncthreads();

    // ---- serial greedy scan: warp 0, active mask in registers (lane l = word l)
    if (t < 32) {
        unsigned act = (t < 6) ? 0xFFFFFFFFu : ((t == 6) ? 0x000000FFu : 0u);
        for (int p = 0; p < TOPK; p++) {
            unsigned rnz = srow[p];                     // broadcast LDS
            if (rnz) {
                unsigned aw = __shfl_sync(0xffffffffu, act, p >> 5);
                if (aw & (1u << (p & 31))) {
                    if (t < NW) act &= ~smat[p * NW + t];
                }
            }
        }
        if (t < NW) sact[t] = act;
    }
    __syncthreads();
    if (t == 0) {
        unsigned c = 0;
        #pragma unroll
        for (int w = 0; w < NW; w++) { spre[w] = c; c += __popc(sact[w]); }
    }
    __syncthreads();

    // ---- parallel write-out: rank = #active with smaller p ----
    if (t < TOPK) {
        unsigned w = (unsigned)t >> 5, bmask = 1u << (t & 31);
        unsigned aw = sact[w];
        if (aw & bmask) {
            int rank = spre[w] + __popc(aw & (bmask - 1));
            out[b * TOPK + rank] = (float)sq[t];
        }
    }
}

// ---------------------------------------------------------------------------
extern "C" void kernel_launch(void* const* d_in, const int* in_sizes, int n_in,
                              void* d_out, int out_size) {
    const float* logits = (const float*)d_in[0];   // [B,Q,C] f32
    const float* seg    = (const float*)d_in[1];   // [B,Q,2] f32
    float* out = (float*)d_out;                    // [2B, TOPK] float32 values

    score_kernel<<<(B * Q) / ROWS, ROWS>>>(logits);          // 2500 blocks
    select_nms_kernel<<<B, 1024>>>(logits, seg, out);        // 32 blocks
}

// round 10
// speedup vs baseline: 3.6227x; 1.0998x over previous
#include <cuda_runtime.h>
#include <math_constants.h>

// Problem constants
#define B 32
#define Q 10000
#define C 80
#define TOPK 200
#define NW 7                   // 224 bits >= 200

// K1 tiling
#define ROWS 128               // queries per block
#define RPAD 21                // row stride in float4 units (odd -> conflict-free LDS)
#define NF4 20                 // 80 floats = 20 float4 per row

// K2 selection
#define VPT 10                 // scores per thread (10 * 1024 >= Q)
#define CANDCAP 512
#define LO_BITS 0x3C000000u    // < bits(1/80): every score exceeds this
#define HI_BITS 0x3F800001u    // > bits(1.0)

// Scratch: scores only (class is computed lazily for selected candidates)
__device__ unsigned int g_score[B * Q];

// ---------------------------------------------------------------------------
// K1: thread-per-query score. Coalesced float4 staging into smem, then each
// thread reduces its own row. Arithmetic replicates the R4 warp version
// bitwise (per-lane partials + xor butterfly 16,8,4,2,1, self-first order).
// score = 1 / sum(exp(l - max))  (max term contributes exp(0)=1)
// ---------------------------------------------------------------------------
__global__ __launch_bounds__(ROWS) void score_kernel(const float* __restrict__ logits) {
    __shared__ float4 s[ROWS * RPAD];          // 43008 B
    int tid = threadIdx.x;

    const float4* gin = (const float4*)logits + (size_t)blockIdx.x * (ROWS * NF4);
    #pragma unroll
    for (int it = 0; it < NF4; it++) {
        int fi = it * ROWS + tid;
        int r = fi / NF4, c = fi % NF4;
        s[r * RPAD + c] = gin[fi];
    }
    __syncthreads();

    const float4* row = s + tid * RPAD;

    float m = -CUDART_INF_F;
    #pragma unroll
    for (int j = 0; j < NF4; j++) {
        float4 f = row[j];
        m = fmaxf(m, fmaxf(fmaxf(f.x, f.y), fmaxf(f.z, f.w)));
    }

    float ep[32];
    #pragma unroll
    for (int l = 0; l < 32; l++) ep[l] = 0.0f;
    #pragma unroll
    for (int j = 0; j < NF4; j++) {
        float4 f = row[j];
        ep[(4 * j + 0) & 31] += expf(f.x - m);
        ep[(4 * j + 1) & 31] += expf(f.y - m);
        ep[(4 * j + 2) & 31] += expf(f.z - m);
        ep[(4 * j + 3) & 31] += expf(f.w - m);
    }
    float e1[32], e2[32], e3[32], e4[32];
    #pragma unroll
    for (int l = 0; l < 32; l++) e1[l] = ep[l] + ep[l ^ 16];
    #pragma unroll
    for (int l = 0; l < 32; l++) e2[l] = e1[l] + e1[l ^ 8];
    #pragma unroll
    for (int l = 0; l < 32; l++) e3[l] = e2[l] + e2[l ^ 4];
    #pragma unroll
    for (int l = 0; l < 32; l++) e4[l] = e3[l] + e3[l ^ 2];
    float e = e4[0] + e4[1];

    float score = 1.0f / e;
    g_score[(size_t)blockIdx.x * ROWS + tid] = __float_as_uint(score);
}

// ---------------------------------------------------------------------------
// K2 (fused, per batch): register-resident binary-search threshold ->
// warp-aggregated compaction -> bitonic sort 512 -> batched lazy argmax ->
// ballot-built suppression bit-matrix -> greedy scan -> float output.
// One block of 1024 threads per batch.
// ---------------------------------------------------------------------------
__global__ __launch_bounds__(1024) void select_nms_kernel(const float* __restrict__ logits,
                                                          const float* __restrict__ seg,
                                                          float* __restrict__ out) {
    __shared__ unsigned int scnt[32];
    __shared__ unsigned int s_tot;
    __shared__ int s_cnt;
    __shared__ unsigned long long ck[CANDCAP];  // 4 KB
    __shared__ float sx1[TOPK], sx2[TOPK];
    __shared__ int   sq[TOPK], scls[TOPK];
    __shared__ unsigned int smat[TOPK * NW];    // 5.6 KB
    __shared__ unsigned int srow[TOPK];
    __shared__ unsigned int sact[NW], spre[NW];

    int b = blockIdx.x;
    int t = threadIdx.x;
    int lane = t & 31, wid = t >> 5;
    const unsigned int* sc = g_score + b * Q;

    // ---- load scores into registers (coalesced; pads = 0, below any thr) ----
    unsigned int v[VPT];
    #pragma unroll
    for (int k = 0; k < VPT; k++) {
        int i = k * 1024 + t;
        v[k] = (i < Q) ? sc[i] : 0u;
    }
    if (t == 0) s_cnt = 0;

    // ---- binary search: largest thr with count(>= thr) >= TOPK; stop when
    //      that count also fits in CANDCAP. Invariant: count(>= lo) >= TOPK. ----
    unsigned int lo = LO_BITS, hi = HI_BITS;
    int cntlo = Q;
    for (int iter = 0; iter < 30 && cntlo > CANDCAP && hi - lo > 1; iter++) {
        unsigned int mid = lo + ((hi - lo) >> 1);
        unsigned int c = 0;
        #pragma unroll
        for (int k = 0; k < VPT; k++) c += (v[k] >= mid);
        unsigned int wc = __reduce_add_sync(0xffffffffu, c);
        if (lane == 0) scnt[wid] = wc;
        __syncthreads();
        if (t < 32) {
            unsigned int tot = __reduce_add_sync(0xffffffffu, scnt[t]);
            if (t == 0) s_tot = tot;
        }
        __syncthreads();
        int cnt = (int)s_tot;
        if (cnt >= TOPK) { lo = mid; cntlo = cnt; } else { hi = mid; }
    }
    unsigned int thr = lo;

    // ---- compact candidates (warp-aggregated atomics; order fixed by sort) ----
    #pragma unroll
    for (int k = 0; k < VPT; k++) {
        int i = k * 1024 + t;
        bool pred = (i < Q) && (v[k] >= thr);
        unsigned int mask = __ballot_sync(0xffffffffu, pred);
        if (mask) {
            int leader = __ffs(mask) - 1;
            int base = 0;
            if (lane == leader) base = atomicAdd(&s_cnt, __popc(mask));
            base = __shfl_sync(0xffffffffu, base, leader);
            if (pred) {
                int pos = base + __popc(mask & ((1u << lane) - 1u));
                if (pos < CANDCAP)
                    ck[pos] = ((unsigned long long)v[k] << 32) |
                              (unsigned int)(~(unsigned int)i);
            }
        }
    }
    __syncthreads();
    int cnt = s_cnt; if (cnt > CANDCAP) cnt = CANDCAP;
    if (t < CANDCAP && t >= cnt) ck[t] = 0ULL;
    __syncthreads();

    // ---- bitonic sort descending (512 keys; threads t<512 active) ----
    for (int k = 2; k <= CANDCAP; k <<= 1) {
        for (int j = k >> 1; j; j >>= 1) {
            if (t < CANDCAP) {
                int ixj = t ^ j;
                if (ixj > t) {
                    bool up = (t & k) == 0;
                    unsigned long long a = ck[t], c2 = ck[ixj];
                    bool sw = up ? (a < c2) : (a > c2);
                    if (sw) { ck[t] = c2; ck[ixj] = a; }
                }
            }
            __syncthreads();
        }
    }

    // ---- gather top-200 + init output ----
    if (t < TOPK) {
        unsigned long long key = ck[t];
        int q = (int)(~(unsigned int)key);
        sq[t] = q;
        int gi = b * Q + q;
        float2 xy = ((const float2*)seg)[gi];
        sx1[t] = xy.x; sx2[t] = xy.y;
        out[b * TOPK + t]       = -1.0f;
        out[(B + b) * TOPK + t] = 0.0f;
    }
    __syncthreads();

    // ---- lazy argmax for the 200 winners: batch all row loads first (MLP) ----
    {
        float a0[7], a1[7], a2[7];
        #pragma unroll
        for (int i = 0; i < 7; i++) {
            int c = wid + i * 32;
            if (c < TOPK) {                     // warp-uniform guard
                const float* p = logits + ((size_t)b * Q + sq[c]) * C;
                a0[i] = p[lane];
                a1[i] = p[32 + lane];
                a2[i] = (lane < 16) ? p[64 + lane] : -CUDART_INF_F;
            }
        }
        #pragma unroll
        for (int i = 0; i < 7; i++) {
            int c = wid + i * 32;
            if (c < TOPK) {
                float m = a0[i]; int mi = lane;
                if (a1[i] > m) { m = a1[i]; mi = 32 + lane; }
                if (a2[i] > m) { m = a2[i]; mi = 64 + lane; }
                #pragma unroll
                for (int o = 16; o; o >>= 1) {
                    float om = __shfl_xor_sync(0xffffffffu, m, o);
                    int   oi = __shfl_xor_sync(0xffffffffu, mi, o);
                    if (om > m || (om == m && oi < mi)) { m = om; mi = oi; }
                }
                if (lane == 0) scls[c] = mi;
            }
        }
    }
    __syncthreads();

    // ---- suppression bit-matrix by ballot: warp (pg,w) owns j-slice [32w,32w+32)
    //      and p-chunk [50pg, 50pg+50). word(p,w) bit b = "p suppresses j=32w+b".
    if (wid < 28) {
        int w = wid % 7, pg = wid / 7;
        int j = w * 32 + lane;
        bool jv = (j < TOPK);
        float jx1 = jv ? sx1[j] : 0.0f;
        float jx2 = jv ? sx2[j] : 0.0f;
        int   jc  = jv ? scls[j] : -1;
        int p0 = pg * 50;
        for (int p = p0; p < p0 + 50; p++) {
            float px1 = sx1[p], px2 = sx2[p];
            int pc = scls[p];
            bool pred = jv && (j > p) && (jc == pc) &&
                        (fminf(jx2, px2) - fmaxf(jx1, px1) > 0.0f);
            unsigned int m = __ballot_sync(0xffffffffu, pred);
            if (lane == 0) smat[p * NW + w] = m;
        }
    }
    __syncthreads();
    if (t < TOPK) {
        unsigned int o = 0;
        #pragma unroll
        for (int w = 0; w < NW; w++) o |= smat[t * NW + w];
        srow[t] = o;
    }
    __syncthreads();

    // ---- serial greedy scan: warp 0, active mask in registers (lane l = word l)
    if (t < 32) {
        unsigned int act = (t < 6) ? 0xFFFFFFFFu : ((t == 6) ? 0x000000FFu : 0u);
        for (int p = 0; p < TOPK; p++) {
            unsigned int rnz = srow[p];                 // broadcast LDS
            if (rnz) {
                unsigned int aw = __shfl_sync(0xffffffffu, act, p >> 5);
                if (aw & (1u << (p & 31))) {
                    if (t < NW) act &= ~smat[p * NW + t];
                }
            }
        }
        if (t < NW) sact[t] = act;
    }
    __syncthreads();
    if (t == 0) {
        unsigned int c = 0;
        #pragma unroll
        for (int w = 0; w < NW; w++) { spre[w] = c; c += __popc(sact[w]); }
    }
    __syncthreads();

    // ---- parallel write-out: rank = #active with smaller p ----
    if (t < TOPK) {
        unsigned int w = (unsigned)t >> 5, bmask = 1u << (t & 31);
        unsigned int aw = sact[w];
        if (aw & bmask) {
            int rank = spre[w] + __popc(aw & (bmask - 1u));
            out[b * TOPK + rank] = (float)sq[t];
        }
    }
}

// ---------------------------------------------------------------------------
extern "C" void kernel_launch(void* const* d_in, const int* in_sizes, int n_in,
                              void* d_out, int out_size) {
    const float* logits = (const float*)d_in[0];   // [B,Q,C] f32
    const float* seg    = (const float*)d_in[1];   // [B,Q,2] f32
    float* out = (float*)d_out;                    // [2B, TOPK] float32 values

    score_kernel<<<(B * Q) / ROWS, ROWS>>>(logits);          // 2500 blocks
    select_nms_kernel<<<B, 1024>>>(logits, seg, out);        // 32 blocks
}

// round 11
// speedup vs baseline: 4.2217x; 1.1653x over previous
#include <cuda_runtime.h>
#include <math_constants.h>

// Problem constants
#define B 32
#define Q 10000
#define C 80
#define TOPK 200
#define NW 7                   // 224 bits >= 200

// K1 tiling
#define ROWS 128               // queries per block
#define RPAD 21                // row stride in float4 units (odd -> conflict-free LDS)
#define NF4 20                 // 80 floats = 20 float4 per row

// K2 selection
#define KTHREADS 512
#define VPT 20                 // scores per thread (20 * 512 >= Q)
#define CANDCAP 512
#define LO_BITS 0x3C000000u    // < bits(1/80): every score exceeds this
#define HI_BITS 0x3F800001u    // > bits(1.0)
#define MAXROUNDS 20
#define CLSCAP 28              // per-class candidate cap (avg is 2.5)

// Scratch: scores only (class is computed lazily for selected candidates)
__device__ unsigned int g_score[B * Q];

// ---------------------------------------------------------------------------
// K1: thread-per-query score (bitwise identical to passing R4/R8 arithmetic).
// ---------------------------------------------------------------------------
__global__ __launch_bounds__(ROWS) void score_kernel(const float* __restrict__ logits) {
    __shared__ float4 s[ROWS * RPAD];          // 43008 B
    int tid = threadIdx.x;

    const float4* gin = (const float4*)logits + (size_t)blockIdx.x * (ROWS * NF4);
    #pragma unroll
    for (int it = 0; it < NF4; it++) {
        int fi = it * ROWS + tid;
        int r = fi / NF4, c = fi % NF4;
        s[r * RPAD + c] = gin[fi];
    }
    __syncthreads();

    const float4* row = s + tid * RPAD;

    float m = -CUDART_INF_F;
    #pragma unroll
    for (int j = 0; j < NF4; j++) {
        float4 f = row[j];
        m = fmaxf(m, fmaxf(fmaxf(f.x, f.y), fmaxf(f.z, f.w)));
    }

    float ep[32];
    #pragma unroll
    for (int l = 0; l < 32; l++) ep[l] = 0.0f;
    #pragma unroll
    for (int j = 0; j < NF4; j++) {
        float4 f = row[j];
        ep[(4 * j + 0) & 31] += expf(f.x - m);
        ep[(4 * j + 1) & 31] += expf(f.y - m);
        ep[(4 * j + 2) & 31] += expf(f.z - m);
        ep[(4 * j + 3) & 31] += expf(f.w - m);
    }
    float e1[32], e2[32], e3[32], e4[32];
    #pragma unroll
    for (int l = 0; l < 32; l++) e1[l] = ep[l] + ep[l ^ 16];
    #pragma unroll
    for (int l = 0; l < 32; l++) e2[l] = e1[l] + e1[l ^ 8];
    #pragma unroll
    for (int l = 0; l < 32; l++) e3[l] = e2[l] + e2[l ^ 4];
    #pragma unroll
    for (int l = 0; l < 32; l++) e4[l] = e3[l] + e3[l ^ 2];
    float e = e4[0] + e4[1];

    float score = 1.0f / e;
    g_score[(size_t)blockIdx.x * ROWS + tid] = __float_as_uint(score);
}

// ---------------------------------------------------------------------------
// K2 (fused, per batch, 512 threads): tri-section threshold -> compaction ->
// register bitonic sort (shfl intra-warp) -> batched argmax -> per-class NMS.
// ---------------------------------------------------------------------------
__global__ __launch_bounds__(KTHREADS) void select_nms_kernel(const float* __restrict__ logits,
                                                              const float* __restrict__ seg,
                                                              float* __restrict__ out) {
    __shared__ unsigned int s_tot[MAXROUNDS];
    __shared__ int s_cnt;
    __shared__ unsigned long long ck[CANDCAP];  // 4 KB
    __shared__ float sx1[TOPK], sx2[TOPK];
    __shared__ int   sq[TOPK], scls[TOPK];
    __shared__ unsigned char sact200[TOPK];
    __shared__ int s_ovf;
    __shared__ unsigned int sact[NW], spre[NW];

    int b = blockIdx.x;
    int t = threadIdx.x;
    int lane = t & 31, wid = t >> 5;
    const unsigned int* sc = g_score + b * Q;

    // ---- load scores into registers (coalesced; pads = 0) ----
    unsigned int v[VPT];
    #pragma unroll
    for (int k = 0; k < VPT; k++) {
        int i = k * KTHREADS + t;
        v[k] = (i < Q) ? sc[i] : 0u;
    }
    if (t < MAXROUNDS) s_tot[t] = 0u;
    if (t == 0) { s_cnt = 0; s_ovf = 0; }
    __syncthreads();

    // ---- tri-section: largest thr with count(>=thr) >= TOPK, stop at <=CANDCAP
    unsigned int lo = LO_BITS, hi = HI_BITS;
    int cntlo = Q;
    for (int r = 0; r < MAXROUNDS; r++) {
        if (cntlo <= CANDCAP) break;
        unsigned int d = (hi - lo) / 3u;
        if (d == 0) break;
        unsigned int m1 = lo + d, m2 = lo + 2u * d;
        unsigned int c1 = 0, c2 = 0;
        #pragma unroll
        for (int k = 0; k < VPT; k++) { c1 += (v[k] >= m1); c2 += (v[k] >= m2); }
        unsigned int packed = (c1 << 16) | c2;
        unsigned int wsum = __reduce_add_sync(0xffffffffu, packed);
        if (lane == 0) atomicAdd(&s_tot[r], wsum);
        __syncthreads();
        unsigned int tot = s_tot[r];
        int tc1 = (int)(tot >> 16), tc2 = (int)(tot & 0xFFFFu);
        if (tc2 >= TOPK)      { lo = m2; cntlo = tc2; }
        else if (tc1 >= TOPK) { lo = m1; cntlo = tc1; hi = m2; }
        else                  { hi = m1; }
    }
    unsigned int thr = lo;

    // ---- compact candidates (warp-aggregated; order fixed by sort) ----
    #pragma unroll
    for (int k = 0; k < VPT; k++) {
        int i = k * KTHREADS + t;
        bool pred = (i < Q) && (v[k] >= thr);
        unsigned int mask = __ballot_sync(0xffffffffu, pred);
        if (mask) {
            int leader = __ffs(mask) - 1;
            int base = 0;
            if (lane == leader) base = atomicAdd(&s_cnt, __popc(mask));
            base = __shfl_sync(0xffffffffu, base, leader);
            if (pred) {
                int pos = base + __popc(mask & ((1u << lane) - 1u));
                if (pos < CANDCAP)
                    ck[pos] = ((unsigned long long)v[k] << 32) |
                              (unsigned int)(~(unsigned int)i);
            }
        }
    }
    __syncthreads();
    int cnt = s_cnt; if (cnt > CANDCAP) cnt = CANDCAP;
    unsigned long long key = (t < cnt) ? ck[t] : 0ULL;
    __syncthreads();

    // ---- bitonic sort descending, key in register, shfl for j<=16 ----
    // take_max = (up == lower): lower index of a pair keeps max in an up region
    #pragma unroll
    for (int k = 2; k <= 32; k <<= 1) {
        #pragma unroll
        for (int j = k >> 1; j >= 1; j >>= 1) {
            unsigned long long part = __shfl_xor_sync(0xffffffffu, key, j);
            bool up = (t & k) == 0, lower = (t & j) == 0;
            bool tm = (up == lower);
            key = (tm == (part > key)) ? part : key;
        }
    }
    #pragma unroll
    for (int k = 64; k <= CANDCAP; k <<= 1) {
        for (int j = k >> 1; j >= 32; j >>= 1) {
            ck[t] = key;
            __syncthreads();
            unsigned long long part = ck[t ^ j];
            __syncthreads();
            bool up = (t & k) == 0, lower = (t & j) == 0;
            bool tm = (up == lower);
            key = (tm == (part > key)) ? part : key;
        }
        #pragma unroll
        for (int j = 16; j >= 1; j >>= 1) {
            unsigned long long part = __shfl_xor_sync(0xffffffffu, key, j);
            bool up = (t & k) == 0, lower = (t & j) == 0;
            bool tm = (up == lower);
            key = (tm == (part > key)) ? part : key;
        }
    }
    ck[t] = key;
    __syncthreads();

    // ---- gather top-200 + init output ----
    if (t < TOPK) {
        unsigned long long kk = ck[t];
        int q = (int)(~(unsigned int)kk);
        sq[t] = q;
        int gi = b * Q + q;
        float2 xy = ((const float2*)seg)[gi];
        sx1[t] = xy.x; sx2[t] = xy.y;
        sact200[t] = 1;
        out[b * TOPK + t]       = -1.0f;
        out[(B + b) * TOPK + t] = 0.0f;
    }
    __syncthreads();

    // ---- batched lazy argmax for the 200 winners (warp per row, stride 16) ----
    {
        float a0[13], a1[13], a2[13];
        #pragma unroll
        for (int i = 0; i < 13; i++) {
            int c = wid + i * 16;
            if (c < TOPK) {                     // warp-uniform guard
                const float* p = logits + ((size_t)b * Q + sq[c]) * C;
                a0[i] = p[lane];
                a1[i] = p[32 + lane];
                a2[i] = (lane < 16) ? p[64 + lane] : -CUDART_INF_F;
            }
        }
        #pragma unroll
        for (int i = 0; i < 13; i++) {
            int c = wid + i * 16;
            if (c < TOPK) {
                float m = a0[i]; int mi = lane;
                if (a1[i] > m) { m = a1[i]; mi = 32 + lane; }
                if (a2[i] > m) { m = a2[i]; mi = 64 + lane; }
                #pragma unroll
                for (int o = 16; o; o >>= 1) {
                    float om = __shfl_xor_sync(0xffffffffu, m, o);
                    int   oi = __shfl_xor_sync(0xffffffffu, mi, o);
                    if (om > m || (om == m && oi < mi)) { m = om; mi = oi; }
                }
                if (lane == 0) scls[c] = mi;
            }
        }
    }
    __syncthreads();

    // ---- per-class greedy NMS: suppression couples only same-class candidates,
    //      so the global greedy recursion decomposes exactly by class. ----
    if (t < C) {
        int list[CLSCAP]; int n = 0;
        #pragma unroll 4
        for (int j = 0; j < TOPK; j++) {
            if (scls[j] == t) { if (n < CLSCAP) list[n] = j; n++; }
        }
        if (n > CLSCAP) {
            s_ovf = 1;
        } else {
            unsigned int actm = (n >= 32) ? 0xFFFFFFFFu : ((1u << n) - 1u);
            for (int a = 0; a < n; a++) {
                if (actm & (1u << a)) {
                    int ja = list[a];
                    float ax1 = sx1[ja], ax2 = sx2[ja];
                    for (int bb = a + 1; bb < n; bb++) {
                        if (actm & (1u << bb)) {
                            int jb = list[bb];
                            float inter = fminf(sx2[jb], ax2) - fmaxf(sx1[jb], ax1);
                            if (inter > 0.0f) actm &= ~(1u << bb);
                        }
                    }
                }
            }
            for (int bb = 0; bb < n; bb++)
                if (!(actm & (1u << bb))) sact200[list[bb]] = 0;
        }
    }
    __syncthreads();
    if (s_ovf) {                                // exact fallback (never expected)
        if (t == 0) {
            for (int j = 0; j < TOPK; j++) sact200[j] = 1;
            for (int p = 0; p < TOPK; p++) {
                if (!sact200[p]) continue;
                float px1 = sx1[p], px2 = sx2[p]; int pc = scls[p];
                for (int j = p + 1; j < TOPK; j++) {
                    if (sact200[j] && scls[j] == pc) {
                        float inter = fminf(sx2[j], px2) - fmaxf(sx1[j], px1);
                        if (inter > 0.0f) sact200[j] = 0;
                    }
                }
            }
        }
    }
    __syncthreads();

    // ---- rank & write-out ----
    if (t < NW * 32) {
        bool pred = (t < TOPK) && (sact200[t] != 0);
        unsigned int m = __ballot_sync(0xffffffffu, pred);
        if (lane == 0) sact[wid] = m;
    }
    __syncthreads();
    if (t == 0) {
        unsigned int c = 0;
        #pragma unroll
        for (int w = 0; w < NW; w++) { spre[w] = c; c += __popc(sact[w]); }
    }
    __syncthreads();
    if (t < TOPK) {
        unsigned int w = (unsigned)t >> 5, bmask = 1u << (t & 31);
        unsigned int aw = sact[w];
        if (aw & bmask) {
            int rank = spre[w] + __popc(aw & (bmask - 1u));
            out[b * TOPK + rank] = (float)sq[t];
        }
    }
}

// ---------------------------------------------------------------------------
extern "C" void kernel_launch(void* const* d_in, const int* in_sizes, int n_in,
                              void* d_out, int out_size) {
    const float* logits = (const float*)d_in[0];   // [B,Q,C] f32
    const float* seg    = (const float*)d_in[1];   // [B,Q,2] f32
    float* out = (float*)d_out;                    // [2B, TOPK] float32 values

    score_kernel<<<(B * Q) / ROWS, ROWS>>>(logits);          // 2500 blocks
    select_nms_kernel<<<B, KTHREADS>>>(logits, seg, out);    // 32 blocks
}